// round 15
// baseline (speedup 1.0000x reference)
#include <cuda_runtime.h>
#include <cuda_bf16.h>
#include <cstdint>

#define LSEQ 2048
#define NBH 128
typedef unsigned long long ull;

// -------- device scratch --------
__device__ float g_Binv2[128 * 1024];    // [kslot][t<1024] parity-grouped cos/sin
__device__ int   g_pmap[64];             // mode m -> kslot (cos; sin at +1)
__device__ uint32_t g_Fm[2][2][64][2048]; // [src][hi/lo][chunk][m*16+kw] bf16x2 words
__device__ float g_G[2][2][NBH][8192];   // [ks][src][bh][pl][e][m]
__device__ float g_X[2][NBH][8192];      // projected spectra
__device__ float g_Z[NBH][8192];         // attention-applied spectra
__device__ float g_Y[NBH * 8192];        // irDFT coeffs, parity-grouped

// -------- f32x2 helpers --------
__device__ __forceinline__ ull dup2(float x) {
    ull r; asm("mov.b64 %0, {%1, %1};" : "=l"(r) : "f"(x)); return r;
}
__device__ __forceinline__ void fma2(ull& d, ull a, ull b) {
    asm("fma.rn.f32x2 %0, %1, %2, %3;" : "=l"(d) : "l"(a), "l"(b), "l"(d));
}
__device__ __forceinline__ ull add2(ull a, ull b) {
    ull r; asm("add.rn.f32x2 %0, %1, %2;" : "=l"(r) : "l"(a), "l"(b)); return r;
}
__device__ __forceinline__ float2 unpk(ull v) {
    float2 r; asm("mov.b64 {%0, %1}, %2;" : "=f"(r.x), "=f"(r.y) : "l"(v)); return r;
}
__device__ __forceinline__ ull neg2(ull v) { return v ^ 0x8000000080000000ULL; }

// -------- bf16 mma (baseline PTX, sm_80+; NOT an 'a' feature) --------
#define MMA16816(d, a0, a1, a2, a3, b0, b1) \
    asm volatile("mma.sync.aligned.m16n8k16.row.col.f32.bf16.bf16.f32 " \
                 "{%0,%1,%2,%3},{%4,%5,%6,%7},{%8,%9},{%0,%1,%2,%3};" \
                 : "+f"((d)[0]), "+f"((d)[1]), "+f"((d)[2]), "+f"((d)[3]) \
                 : "r"(a0), "r"(a1), "r"(a2), "r"(a3), "r"(b0), "r"(b1))

__device__ __forceinline__ uint32_t pack_bf16x2(float lo, float hi) {
    __nv_bfloat162 v;
    v.x = __float2bfloat16(lo);
    v.y = __float2bfloat16(hi);
    return *(uint32_t*)&v;
}

// ---------------- init: parity-grouped inverse basis ----------------
__global__ void k_init_binv2(const int* __restrict__ idxq) {
    __shared__ int sidx[64];
    int tid = threadIdx.x;
    if (tid < 64) sidx[tid] = idxq[tid];
    __syncthreads();
    int gidx = blockIdx.x * blockDim.x + tid;
    if (gidx >= 1024 * 64) return;
    int t = gidx >> 6, m = gidx & 63;
    int f = sidx[m];
    int par = f & 1;
    int rank = 0;
    for (int mm = 0; mm < m; mm++) rank += ((sidx[mm] & 1) == par);
    int slot = par * 64 + 2 * rank;
    int r = (f * t) & (LSEQ - 1);
    float sn, cs;
    sincospif((float)r * (1.0f / 1024.0f), &sn, &cs);
    g_Binv2[slot * 1024 + t]       = cs;
    g_Binv2[(slot + 1) * 1024 + t] = sn;
    if (t == 0) g_pmap[m] = slot;
}

// ---------------- init: bf16 hi/lo forward basis tables (fragment-ready) ----------------
// Row m<64: cos(2*pi*f_m*t/L); m>=64: -sin. Word kw packs (t=c*32+2kw, t+1).
__global__ void k_init_fm(const int* __restrict__ idx, int src) {
    int gidx = blockIdx.x * blockDim.x + threadIdx.x;
    if (gidx >= 64 * 128 * 16) return;
    int c  = gidx >> 11;
    int m  = (gidx >> 4) & 127;
    int kw = gidx & 15;
    int f = __ldg(&idx[m & 63]);
    int t0 = c * 32 + 2 * kw;
    float v[2];
#pragma unroll
    for (int u = 0; u < 2; u++) {
        int r = (f * (t0 + u)) & (LSEQ - 1);
        float sn, cs;
        sincospif((float)r * (1.0f / 1024.0f), &sn, &cs);
        v[u] = (m < 64) ? cs : -sn;
    }
    float h0 = __bfloat162float(__float2bfloat16(v[0]));
    float h1 = __bfloat162float(__float2bfloat16(v[1]));
    g_Fm[src][0][c][m * 16 + kw] = pack_bf16x2(v[0], v[1]);
    g_Fm[src][1][c][m * 16 + kw] = pack_bf16x2(v[0] - h0, v[1] - h1);
}

// ---------------- K1: mma.sync bf16-split forward DFT ----------------
// grid 512: (ks, bh, src). 256 thr (8 warps). D[128 basis][64 e], K=1024/block.
// 3 split terms: Fh*xh + Fh*xl + Fl*xh. Chunk KC=32 (2 k16 steps).
__global__ void __launch_bounds__(256) k_fwd_mma(const float* __restrict__ q,
                                                 const float* __restrict__ kk_) {
    __shared__ uint32_t sAh[128 * 20];   // word stride 20: conflict-free A frags
    __shared__ uint32_t sAl[128 * 20];
    __shared__ uint32_t sBh[16 * 72];    // word stride 72: conflict-free B frags
    __shared__ uint32_t sBl[16 * 72];

    int bx = blockIdx.x;
    int ks  = bx & 1;
    int bh  = (bx >> 1) & 127;
    int src = bx >> 8;
    const float* x = (src == 0 ? q : kk_)
                   + (size_t)(bh >> 3) * (LSEQ * 512) + (bh & 7) * 64;
    const uint32_t* TAh = &g_Fm[src][0][0][0];
    const uint32_t* TAl = &g_Fm[src][1][0][0];

    int tid = threadIdx.x;
    int w = tid >> 5, lane = tid & 31;
    int g = lane >> 2, tg = lane & 3;

    float d[8][4];
#pragma unroll
    for (int j = 0; j < 8; j++)
#pragma unroll
        for (int i = 0; i < 4; i++) d[j][i] = 0.f;

    int kpL = tid >> 4;               // B stage: 0..15
    int e0L = (tid & 15) * 4;

    for (int cc = 0; cc < 32; cc++) {
        int c = ks * 32 + cc;         // global chunk (t = c*32 ..)
        if (cc) __syncthreads();
        // stage A hi/lo: 512 uint4 per table, 2 per thread
        const uint4* sH = (const uint4*)(TAh + (size_t)c * 2048);
        const uint4* sL = (const uint4*)(TAl + (size_t)c * 2048);
#pragma unroll
        for (int r = 0; r < 2; r++) {
            int idx = tid + r * 256;
            int row = idx >> 2, qd = idx & 3;
            *(uint4*)&sAh[row * 20 + qd * 4] = sH[idx];
            *(uint4*)&sAl[row * 20 + qd * 4] = sL[idx];
        }
        // stage B: x rows t0=c*32+2kp, t0+1; split bf16 hi/lo; pack t-pairs
        {
            const float* xr0 = x + (size_t)(c * 32 + 2 * kpL) * 512;
            float4 xa = *(const float4*)(xr0 + e0L);
            float4 xb = *(const float4*)(xr0 + 512 + e0L);
            float av[4] = {xa.x, xa.y, xa.z, xa.w};
            float bv[4] = {xb.x, xb.y, xb.z, xb.w};
            uint32_t hw[4], lw[4];
#pragma unroll
            for (int u = 0; u < 4; u++) {
                float ah = __bfloat162float(__float2bfloat16(av[u]));
                float bhf = __bfloat162float(__float2bfloat16(bv[u]));
                hw[u] = pack_bf16x2(av[u], bv[u]);
                lw[u] = pack_bf16x2(av[u] - ah, bv[u] - bhf);
            }
            *(uint4*)&sBh[kpL * 72 + e0L] = make_uint4(hw[0], hw[1], hw[2], hw[3]);
            *(uint4*)&sBl[kpL * 72 + e0L] = make_uint4(lw[0], lw[1], lw[2], lw[3]);
        }
        __syncthreads();

        int rowA = (16 * w + g) * 20;
#pragma unroll
        for (int s = 0; s < 2; s++) {
            int ka = 8 * s + tg;
            uint32_t ah0 = sAh[rowA + ka];
            uint32_t ah1 = sAh[rowA + 160 + ka];
            uint32_t ah2 = sAh[rowA + ka + 4];
            uint32_t ah3 = sAh[rowA + 160 + ka + 4];
            uint32_t al0 = sAl[rowA + ka];
            uint32_t al1 = sAl[rowA + 160 + ka];
            uint32_t al2 = sAl[rowA + ka + 4];
            uint32_t al3 = sAl[rowA + 160 + ka + 4];
            int kb0 = (8 * s + tg) * 72;
            int kb1 = (8 * s + tg + 4) * 72;
#pragma unroll
            for (int j = 0; j < 8; j++) {
                int n = 8 * j + g;
                uint32_t bh0 = sBh[kb0 + n], bh1 = sBh[kb1 + n];
                uint32_t bl0 = sBl[kb0 + n], bl1 = sBl[kb1 + n];
                MMA16816(d[j], ah0, ah1, ah2, ah3, bh0, bh1);
                MMA16816(d[j], ah0, ah1, ah2, ah3, bl0, bl1);
                MMA16816(d[j], al0, al1, al2, al3, bh0, bh1);
            }
        }
    }

    // epilogue: D[16w+g][8j+2tg(,+1)] and row+8 -> g_G[ks][src][bh][pl][e][mode]
    float* G = g_G[ks][src][bh];
    int r0 = 16 * w + g, r1 = r0 + 8;
    int pl0 = (r0 >> 6) * 4096, m0 = r0 & 63;
    int pl1 = (r1 >> 6) * 4096, m1 = r1 & 63;
#pragma unroll
    for (int j = 0; j < 8; j++) {
        int e0c = 8 * j + 2 * tg;
        G[pl0 + e0c * 64 + m0]       = d[j][0];
        G[pl0 + (e0c + 1) * 64 + m0] = d[j][1];
        G[pl1 + e0c * 64 + m1]       = d[j][2];
        G[pl1 + (e0c + 1) * 64 + m1] = d[j][3];
    }
}

// ---------------- K2a: projections X = W*G + bias (ksplit sum) ----------------
__global__ void __launch_bounds__(256) k_proj(
    const float* __restrict__ wq_w, const float* __restrict__ wq_b,
    const float* __restrict__ wk_w, const float* __restrict__ wk_b,
    const int* __restrict__ idxq,   const int* __restrict__ idxkv) {
    extern __shared__ float sm[];
    float* sG = sm;          // 8192
    float* sW = sm + 8192;   // 4096

    int bx = blockIdx.x;
    int src = bx >> 7;
    int bh  = bx & 127;
    const float* Wm   = src ? wk_w : wq_w;
    const float* bias = src ? wk_b : wq_b;
    const int*   idx  = src ? idxkv : idxq;
    int tid = threadIdx.x;

#pragma unroll
    for (int r = 0; r < 8; r++) {
        float4 a = ((const float4*)(g_G[0][src][bh]))[r * 256 + tid];
        float4 a1 = ((const float4*)(g_G[1][src][bh]))[r * 256 + tid];
        a.x += a1.x; a.y += a1.y; a.z += a1.z; a.w += a1.w;
        ((float4*)sG)[r * 256 + tid] = a;
    }
#pragma unroll
    for (int r = 0; r < 4; r++)
        ((float4*)sW)[r * 256 + tid] = ((const float4*)Wm)[r * 256 + tid];
    __syncthreads();

    float* Xout = g_X[src][bh];
#pragma unroll 1
    for (int kk = 0; kk < 8; kk++) {
        int pidx = kk * 256 + tid;
        int ep = pidx >> 5, mp = pidx & 31;
        ull ar0 = 0ULL, ar1 = 0ULL, ai0 = 0ULL, ai1 = 0ULL;
#pragma unroll 8
        for (int e = 0; e < 32; e++) {
            ull wd0 = dup2(sW[ep * 64 + e]);
            ull wd1 = dup2(sW[ep * 64 + 32 + e]);
            fma2(ar0, wd0, *(ull*)&sG[e * 64 + mp * 2]);
            fma2(ar1, wd1, *(ull*)&sG[(32 + e) * 64 + mp * 2]);
            fma2(ai0, wd0, *(ull*)&sG[4096 + e * 64 + mp * 2]);
            fma2(ai1, wd1, *(ull*)&sG[4096 + (32 + e) * 64 + mp * 2]);
        }
        float2 arf = unpk(add2(ar0, ar1)), aif = unpk(add2(ai0, ai1));
        float bb = 2048.f * bias[ep];
        if (idx[2 * mp] == 0)     arf.x += bb;
        if (idx[2 * mp + 1] == 0) arf.y += bb;
        *(float2*)&Xout[ep * 64 + mp * 2] = arf;
        *(float2*)&Xout[4096 + ep * 64 + mp * 2] = aif;
    }
}

// ---------------- K2b: scores + tanh + apply -> Z ----------------
__global__ void __launch_bounds__(256) k_attn(const int* __restrict__ idxq) {
    extern __shared__ float sm[];
    float* sXq = sm;            // 2048
    float* sXk = sm + 2048;     // 8192
    float* sS  = sm + 10240;    // 2048

    int bx = blockIdx.x;
    int bh = bx >> 2;
    int xc = bx & 3;
    int x0 = xc * 16;
    int tid = threadIdx.x;

    const float* Xq = g_X[0][bh];
#pragma unroll
    for (int r = 0; r < 2; r++) {
        int idx = r * 256 + tid;
        int p = idx >> 8, rem = idx & 255;
        int e = rem >> 2, c = rem & 3;
        ((float4*)sXq)[idx] = *(const float4*)(Xq + p * 4096 + e * 64 + x0 + c * 4);
    }
    const float4* Xk4 = (const float4*)(g_X[1][bh]);
#pragma unroll
    for (int r = 0; r < 8; r++)
        ((float4*)sXk)[r * 256 + tid] = Xk4[r * 256 + tid];
    __syncthreads();

#pragma unroll 1
    for (int kk = 0; kk < 2; kk++) {
        int pidx = kk * 256 + tid;
        int y = pidx >> 3, xp = pidx & 7;
        ull sr0 = 0ULL, sr1 = 0ULL, si0 = 0ULL, si1 = 0ULL;
#pragma unroll 8
        for (int e = 0; e < 32; e++) {
            ull qr0 = *(ull*)&sXq[e * 16 + xp * 2];
            ull qi0 = *(ull*)&sXq[1024 + e * 16 + xp * 2];
            ull qr1 = *(ull*)&sXq[(32 + e) * 16 + xp * 2];
            ull qi1 = *(ull*)&sXq[1024 + (32 + e) * 16 + xp * 2];
            float kr0 = sXk[e * 64 + y],        ki0 = sXk[4096 + e * 64 + y];
            float kr1 = sXk[(32 + e) * 64 + y], ki1 = sXk[4096 + (32 + e) * 64 + y];
            fma2(sr0, qr0, dup2(kr0)); fma2(sr0, qi0, dup2(-ki0));
            fma2(si0, qr0, dup2(ki0)); fma2(si0, qi0, dup2(kr0));
            fma2(sr1, qr1, dup2(kr1)); fma2(sr1, qi1, dup2(-ki1));
            fma2(si1, qr1, dup2(ki1)); fma2(si1, qi1, dup2(kr1));
        }
        float2 srf = unpk(add2(sr0, sr1)), sif = unpk(add2(si0, si1));
        srf.x = tanhf(srf.x); srf.y = tanhf(srf.y);
        sif.x = tanhf(sif.x); sif.y = tanhf(sif.y);
        *(float2*)&sS[y * 16 + xp * 2] = srf;
        *(float2*)&sS[1024 + y * 16 + xp * 2] = sif;
    }
    __syncthreads();

    float* Zout = g_Z[bh];
#pragma unroll 1
    for (int kk = 0; kk < 2; kk++) {
        int pidx = kk * 256 + tid;
        int e = pidx >> 3, xp = pidx & 7;
        ull zr0 = 0ULL, zr1 = 0ULL, zi0 = 0ULL, zi1 = 0ULL;
#pragma unroll 8
        for (int y = 0; y < 32; y++) {
            ull s_r0 = *(ull*)&sS[y * 16 + xp * 2];
            ull s_i0 = *(ull*)&sS[1024 + y * 16 + xp * 2];
            ull s_r1 = *(ull*)&sS[(32 + y) * 16 + xp * 2];
            ull s_i1 = *(ull*)&sS[1024 + (32 + y) * 16 + xp * 2];
            float kr0 = sXk[e * 64 + y],      ki0 = sXk[4096 + e * 64 + y];
            float kr1 = sXk[e * 64 + 32 + y], ki1 = sXk[4096 + e * 64 + 32 + y];
            fma2(zr0, s_r0, dup2(kr0)); fma2(zr0, s_i0, dup2(-ki0));
            fma2(zi0, s_r0, dup2(ki0)); fma2(zi0, s_i0, dup2(kr0));
            fma2(zr1, s_r1, dup2(kr1)); fma2(zr1, s_i1, dup2(-ki1));
            fma2(zi1, s_r1, dup2(ki1)); fma2(zi1, s_i1, dup2(kr1));
        }
        float2 zrf = unpk(add2(zr0, zr1)), zif = unpk(add2(zi0, zi1));
        *(float2*)&Zout[e * 64 + x0 + xp * 2]        = zrf;
        *(float2*)&Zout[4096 + e * 64 + x0 + xp * 2] = zif;
    }
}

// ---------------- K2c: apply complex weights; parity-grouped Y ----------------
__global__ void __launch_bounds__(256) k_apply(
    const float* __restrict__ W1, const float* __restrict__ W2,
    const int* __restrict__ idxq) {
    extern __shared__ ull smu[];
    ull* sWr = smu;
    ull* sWi = smu + 4096;
    ull* sZ  = smu + 8192;

    int bx = blockIdx.x;
    int h   = bx >> 5;
    int xp2 = bx & 31;
    int x0  = xp2 * 2;
    int tid = threadIdx.x;

    const float* W1h = W1 + (size_t)h * 262144 + x0;
    const float* W2h = W2 + (size_t)h * 262144 + x0;
#pragma unroll
    for (int r = 0; r < 16; r++) {
        int idx = r * 256 + tid;
        sWr[idx] = *(const ull*)(W1h + (size_t)idx * 64);
        sWi[idx] = *(const ull*)(W2h + (size_t)idx * 64);
    }
#pragma unroll
    for (int r = 0; r < 8; r++) {
        int idx = r * 256 + tid;
        int b = idx >> 7, rem = idx & 127;
        sZ[idx] = *(const ull*)(g_Z[b * 8 + h] + (rem >> 6) * 4096 + (rem & 63) * 64 + x0);
    }
    __syncthreads();

    int o  = tid & 63;
    int bq = tid >> 6;

    ull yr[4], yi[4];
#pragma unroll
    for (int j = 0; j < 4; j++) { yr[j] = 0ULL; yi[j] = 0ULL; }

#pragma unroll 4
    for (int e = 0; e < 64; e++) {
        ull wr = sWr[e * 64 + o];
        ull wi = sWi[e * 64 + o];
#pragma unroll
        for (int j = 0; j < 4; j++) {
            int b = bq + j * 4;
            ull zr = sZ[b * 128 + e];
            ull zi = sZ[b * 128 + 64 + e];
            fma2(yr[j], zr, wr); fma2(yr[j], neg2(zi), wi);
            fma2(yi[j], zr, wi); fma2(yi[j], zi, wr);
        }
    }

    const float SC = 1.862645149230957e-9f;  // 2^-29
    int f0 = idxq[x0], f1 = idxq[x0 + 1];
    bool dc0 = (f0 == 0) | (f0 == 1024);
    bool dc1 = (f1 == 0) | (f1 == 1024);
    float ca0 = dc0 ? SC : 2.f * SC;
    float ca1 = dc1 ? SC : 2.f * SC;
    float cb0 = dc0 ? 0.f : -2.f * SC;
    float cb1 = dc1 ? 0.f : -2.f * SC;
    int s0 = g_pmap[x0], s1 = g_pmap[x0 + 1];

#pragma unroll
    for (int j = 0; j < 4; j++) {
        int b = bq + j * 4;
        float* Yout = g_Y + (size_t)(b * 8 + h) * 8192;
        float2 r = unpk(yr[j]), im = unpk(yi[j]);
        Yout[s0 * 64 + o]       = r.x * ca0;
        Yout[(s0 + 1) * 64 + o] = im.x * cb0;
        Yout[s1 * 64 + o]       = r.y * ca1;
        Yout[(s1 + 1) * 64 + o] = im.y * cb1;
    }
}

// ---------------- K3: folded inverse DFT GEMM ----------------
__global__ void __launch_bounds__(256) k_inv2(float* __restrict__ out) {
    __shared__ float As[2][16 * 64];
    __shared__ float Bs[2][16 * 128];

    int bh = blockIdx.y;
    int t0 = blockIdx.x * 128;
    int tid = threadIdx.x;
    int ty = tid >> 4, tx = tid & 15;
    int o0 = ty * 4;
    const float* Yb = g_Y + (size_t)bh * 8192;

    int rA = tid >> 4, cA = (tid & 15) * 4;

    ull acc[2][4][4];
#pragma unroll
    for (int p = 0; p < 2; p++)
#pragma unroll
        for (int i = 0; i < 4; i++)
#pragma unroll
            for (int j = 0; j < 4; j++) acc[p][i][j] = 0ULL;

    float4 pA, pB[2];
    pA = *(const float4*)(Yb + (size_t)rA * 64 + cA);
#pragma unroll
    for (int r = 0; r < 2; r++) {
        int idx = tid + r * 256;
        int row = idx >> 5, col = (idx & 31) * 4;
        pB[r] = *(const float4*)(g_Binv2 + (size_t)row * 1024 + t0 + col);
    }
    *(float4*)&As[0][rA * 64 + cA] = pA;
#pragma unroll
    for (int r = 0; r < 2; r++) {
        int idx = tid + r * 256;
        int row = idx >> 5, col = (idx & 31) * 4;
        *(float4*)&Bs[0][row * 128 + col] = pB[r];
    }
    __syncthreads();

#pragma unroll
    for (int kt = 0; kt < 8; kt++) {
        int p = kt & 1;
        if (kt + 1 < 8) {
            int k0 = (kt + 1) * 16;
            pA = *(const float4*)(Yb + (size_t)(k0 + rA) * 64 + cA);
#pragma unroll
            for (int r = 0; r < 2; r++) {
                int idx = tid + r * 256;
                int row = idx >> 5, col = (idx & 31) * 4;
                pB[r] = *(const float4*)(g_Binv2 + (size_t)(k0 + row) * 1024 + t0 + col);
            }
        }
        const int pg = kt >> 2;
#pragma unroll
        for (int tk = 0; tk < 16; tk++) {
            float4 a = *(float4*)&As[p][tk * 64 + o0];
            ull bv[4];
#pragma unroll
            for (int j = 0; j < 4; j++) bv[j] = *(ull*)&Bs[p][tk * 128 + j * 32 + tx * 2];
            ull ad[4] = {dup2(a.x), dup2(a.y), dup2(a.z), dup2(a.w)};
#pragma unroll
            for (int i = 0; i < 4; i++)
#pragma unroll
                for (int j = 0; j < 4; j++) fma2(acc[pg][i][j], ad[i], bv[j]);
        }
        if (kt + 1 < 8) {
            int np = (kt + 1) & 1;
            *(float4*)&As[np][rA * 64 + cA] = pA;
#pragma unroll
            for (int r = 0; r < 2; r++) {
                int idx = tid + r * 256;
                int row = idx >> 5, col = (idx & 31) * 4;
                *(float4*)&Bs[np][row * 128 + col] = pB[r];
            }
            __syncthreads();
        }
    }

    float* op = out + (size_t)bh * 64 * LSEQ;
#pragma unroll
    for (int i = 0; i < 4; i++) {
        int o = o0 + i;
#pragma unroll
        for (int j = 0; j < 4; j++) {
            int tsub = j * 32 + tx * 2;
            ull E = acc[0][i][j], O = acc[1][i][j];
            *(ull*)(op + (size_t)o * LSEQ + t0 + tsub)        = add2(E, O);
            *(ull*)(op + (size_t)o * LSEQ + 1024 + t0 + tsub) = add2(E, neg2(O));
        }
    }
}

// ---------------- launch ----------------
extern "C" void kernel_launch(void* const* d_in, const int* in_sizes, int n_in,
                              void* d_out, int out_size) {
    const float* q    = (const float*)d_in[0];
    const float* k    = (const float*)d_in[1];
    const float* wq_w = (const float*)d_in[3];
    const float* wq_b = (const float*)d_in[4];
    const float* wk_w = (const float*)d_in[5];
    const float* wk_b = (const float*)d_in[6];
    const float* W1   = (const float*)d_in[9];
    const float* W2   = (const float*)d_in[10];
    const int*  idxq  = (const int*)d_in[11];
    const int*  idxkv = (const int*)d_in[12];
    float* out = (float*)d_out;

    cudaFuncSetAttribute(k_proj,  cudaFuncAttributeMaxDynamicSharedMemorySize, 49152);
    cudaFuncSetAttribute(k_attn,  cudaFuncAttributeMaxDynamicSharedMemorySize, 49152);
    cudaFuncSetAttribute(k_apply, cudaFuncAttributeMaxDynamicSharedMemorySize, 81920);

    k_init_binv2<<<256, 256>>>(idxq);
    k_init_fm<<<512, 256>>>(idxq, 0);
    k_init_fm<<<512, 256>>>(idxkv, 1);
    k_fwd_mma<<<512, 256>>>(q, k);
    k_proj<<<256, 256, 49152>>>(wq_w, wq_b, wk_w, wk_b, idxq, idxkv);
    k_attn<<<512, 256, 49152>>>(idxq);
    k_apply<<<256, 256, 81920>>>(W1, W2, idxq);
    k_inv2<<<dim3(8, 128), 256>>>(out);
}

// round 16
// speedup vs baseline: 1.0970x; 1.0970x over previous
#include <cuda_runtime.h>
#include <cuda_bf16.h>
#include <cstdint>

#define LSEQ 2048
#define NBH 128
typedef unsigned long long ull;

// -------- device scratch --------
__device__ float g_Binv2[128 * 1024];    // [kslot][t<1024] parity-grouped cos/sin
__device__ int   g_pmap[64];             // mode m -> kslot (cos; sin at +1)
__device__ uint32_t g_Fm[2][2][64][2048]; // [src][hi/lo][chunk][m*16+kw] bf16x2 words
__device__ float g_G[2][2][NBH][8192];   // [ks][src][bh][pl][e][m]
__device__ float g_X[2][NBH][8192];      // projected spectra
__device__ float g_Z[NBH][8192];         // attention-applied spectra
__device__ float g_Y[NBH * 8192];        // irDFT coeffs, parity-grouped

// -------- f32x2 helpers --------
__device__ __forceinline__ ull dup2(float x) {
    ull r; asm("mov.b64 %0, {%1, %1};" : "=l"(r) : "f"(x)); return r;
}
__device__ __forceinline__ void fma2(ull& d, ull a, ull b) {
    asm("fma.rn.f32x2 %0, %1, %2, %3;" : "=l"(d) : "l"(a), "l"(b), "l"(d));
}
__device__ __forceinline__ ull add2(ull a, ull b) {
    ull r; asm("add.rn.f32x2 %0, %1, %2;" : "=l"(r) : "l"(a), "l"(b)); return r;
}
__device__ __forceinline__ float2 unpk(ull v) {
    float2 r; asm("mov.b64 {%0, %1}, %2;" : "=f"(r.x), "=f"(r.y) : "l"(v)); return r;
}
__device__ __forceinline__ ull neg2(ull v) { return v ^ 0x8000000080000000ULL; }

// -------- bf16 mma + cp.async (baseline PTX sm_80+, no 'a' features) --------
#define MMA16816(d, a0, a1, a2, a3, b0, b1) \
    asm volatile("mma.sync.aligned.m16n8k16.row.col.f32.bf16.bf16.f32 " \
                 "{%0,%1,%2,%3},{%4,%5,%6,%7},{%8,%9},{%0,%1,%2,%3};" \
                 : "+f"((d)[0]), "+f"((d)[1]), "+f"((d)[2]), "+f"((d)[3]) \
                 : "r"(a0), "r"(a1), "r"(a2), "r"(a3), "r"(b0), "r"(b1))

__device__ __forceinline__ uint32_t smem_u32(const void* p) {
    uint32_t a;
    asm("{ .reg .u64 t; cvta.to.shared.u64 t, %1; cvt.u32.u64 %0, t; }" : "=r"(a) : "l"(p));
    return a;
}
__device__ __forceinline__ void cpasync16(uint32_t dst, const void* src) {
    asm volatile("cp.async.ca.shared.global [%0], [%1], 16;" :: "r"(dst), "l"(src));
}
#define CP_COMMIT() asm volatile("cp.async.commit_group;" ::: "memory")
#define CP_WAIT0()  asm volatile("cp.async.wait_group 0;" ::: "memory")

__device__ __forceinline__ uint32_t pack_bf16x2(float lo, float hi) {
    __nv_bfloat162 v;
    v.x = __float2bfloat16(lo);
    v.y = __float2bfloat16(hi);
    return *(uint32_t*)&v;
}

// ---------------- init: parity-grouped inverse basis ----------------
__global__ void k_init_binv2(const int* __restrict__ idxq) {
    __shared__ int sidx[64];
    int tid = threadIdx.x;
    if (tid < 64) sidx[tid] = idxq[tid];
    __syncthreads();
    int gidx = blockIdx.x * blockDim.x + tid;
    if (gidx >= 1024 * 64) return;
    int t = gidx >> 6, m = gidx & 63;
    int f = sidx[m];
    int par = f & 1;
    int rank = 0;
    for (int mm = 0; mm < m; mm++) rank += ((sidx[mm] & 1) == par);
    int slot = par * 64 + 2 * rank;
    int r = (f * t) & (LSEQ - 1);
    float sn, cs;
    sincospif((float)r * (1.0f / 1024.0f), &sn, &cs);
    g_Binv2[slot * 1024 + t]       = cs;
    g_Binv2[(slot + 1) * 1024 + t] = sn;
    if (t == 0) g_pmap[m] = slot;
}

// ---------------- init: bf16 hi/lo forward basis tables ----------------
__global__ void k_init_fm(const int* __restrict__ idx, int src) {
    int gidx = blockIdx.x * blockDim.x + threadIdx.x;
    if (gidx >= 64 * 128 * 16) return;
    int c  = gidx >> 11;
    int m  = (gidx >> 4) & 127;
    int kw = gidx & 15;
    int f = __ldg(&idx[m & 63]);
    int t0 = c * 32 + 2 * kw;
    float v[2];
#pragma unroll
    for (int u = 0; u < 2; u++) {
        int r = (f * (t0 + u)) & (LSEQ - 1);
        float sn, cs;
        sincospif((float)r * (1.0f / 1024.0f), &sn, &cs);
        v[u] = (m < 64) ? cs : -sn;
    }
    float h0 = __bfloat162float(__float2bfloat16(v[0]));
    float h1 = __bfloat162float(__float2bfloat16(v[1]));
    g_Fm[src][0][c][m * 16 + kw] = pack_bf16x2(v[0], v[1]);
    g_Fm[src][1][c][m * 16 + kw] = pack_bf16x2(v[0] - h0, v[1] - h1);
}

// ---------------- K1: pipelined mma.sync bf16-split forward DFT ----------------
// grid 512: (ks, bh, src). 256 thr. Double-buffered: A via cp.async, B via reg prefetch.
// Per-buf words: Ah 2560 | Al 2560 | Bh 1152 | Bl 1152 = 7424 (29696 B); x2 bufs.
__global__ void __launch_bounds__(256) k_fwd_mma2(const float* __restrict__ q,
                                                  const float* __restrict__ kk_) {
    extern __shared__ uint32_t smw[];
    const int WB = 7424;            // words per buffer
    const int OAL = 2560, OBH = 5120, OBL = 6272;

    int bx = blockIdx.x;
    int ks  = bx & 1;
    int bh  = (bx >> 1) & 127;
    int src = bx >> 8;
    const float* x = (src == 0 ? q : kk_)
                   + (size_t)(bh >> 3) * (LSEQ * 512) + (bh & 7) * 64;
    const uint32_t* TAh = &g_Fm[src][0][0][0];
    const uint32_t* TAl = &g_Fm[src][1][0][0];

    int tid = threadIdx.x;
    int w = tid >> 5, lane = tid & 31;
    int g = lane >> 2, tg = lane & 3;

    // A cp.async indices (2 uint4/thread/table)
    int iA0 = tid, iA1 = tid + 256;
    int rowA0 = iA0 >> 2, qdA0 = iA0 & 3;
    int rowA1 = iA1 >> 2, qdA1 = iA1 & 3;
    uint32_t dAh0 = smem_u32(smw) + (rowA0 * 20 + qdA0 * 4) * 4;
    uint32_t dAh1 = smem_u32(smw) + (rowA1 * 20 + qdA1 * 4) * 4;

    // B staging indices
    int kpL = tid >> 4;
    int e0L = (tid & 15) * 4;

    float d[8][4];
#pragma unroll
    for (int j = 0; j < 8; j++)
#pragma unroll
        for (int i = 0; i < 4; i++) d[j][i] = 0.f;

    auto issueA = [&](int c, int p) {
        uint32_t off = (uint32_t)p * WB * 4;
        const char* sH = (const char*)(TAh + (size_t)c * 2048);
        const char* sL = (const char*)(TAl + (size_t)c * 2048);
        cpasync16(dAh0 + off, sH + iA0 * 16);
        cpasync16(dAh1 + off, sH + iA1 * 16);
        cpasync16(dAh0 + off + OAL * 4, sL + iA0 * 16);
        cpasync16(dAh1 + off + OAL * 4, sL + iA1 * 16);
        CP_COMMIT();
    };
    auto loadB = [&](int c, float4& xa, float4& xb) {
        const float* xr0 = x + (size_t)(c * 32 + 2 * kpL) * 512;
        xa = *(const float4*)(xr0 + e0L);
        xb = *(const float4*)(xr0 + 512 + e0L);
    };
    auto storeB = [&](int p, const float4& xa, const float4& xb) {
        float av[4] = {xa.x, xa.y, xa.z, xa.w};
        float bv[4] = {xb.x, xb.y, xb.z, xb.w};
        uint32_t hw[4], lw[4];
#pragma unroll
        for (int u = 0; u < 4; u++) {
            float ah = __bfloat162float(__float2bfloat16(av[u]));
            float bhf = __bfloat162float(__float2bfloat16(bv[u]));
            hw[u] = pack_bf16x2(av[u], bv[u]);
            lw[u] = pack_bf16x2(av[u] - ah, bv[u] - bhf);
        }
        uint32_t* B = smw + p * WB;
        *(uint4*)&B[OBH + kpL * 72 + e0L] = make_uint4(hw[0], hw[1], hw[2], hw[3]);
        *(uint4*)&B[OBL + kpL * 72 + e0L] = make_uint4(lw[0], lw[1], lw[2], lw[3]);
    };

    // prologue
    float4 xa, xb;
    issueA(ks * 32, 0);
    loadB(ks * 32, xa, xb);
    storeB(0, xa, xb);
    CP_WAIT0();
    __syncthreads();

    for (int cc = 0; cc < 32; cc++) {
        int p = cc & 1;
        if (cc + 1 < 32) {
            issueA(ks * 32 + cc + 1, p ^ 1);
            loadB(ks * 32 + cc + 1, xa, xb);
        }
        // MMA compute on buf p
        uint32_t* Ah = smw + p * WB;
        uint32_t* Al = Ah + OAL;
        uint32_t* Bh = Ah + OBH;
        uint32_t* Bl = Ah + OBL;
        int rowA = (16 * w + g) * 20;
#pragma unroll
        for (int s = 0; s < 2; s++) {
            int ka = 8 * s + tg;
            uint32_t ah0 = Ah[rowA + ka];
            uint32_t ah1 = Ah[rowA + 160 + ka];
            uint32_t ah2 = Ah[rowA + ka + 4];
            uint32_t ah3 = Ah[rowA + 160 + ka + 4];
            uint32_t al0 = Al[rowA + ka];
            uint32_t al1 = Al[rowA + 160 + ka];
            uint32_t al2 = Al[rowA + ka + 4];
            uint32_t al3 = Al[rowA + 160 + ka + 4];
            int kb0 = (8 * s + tg) * 72;
            int kb1 = (8 * s + tg + 4) * 72;
#pragma unroll
            for (int j = 0; j < 8; j++) {
                int n = 8 * j + g;
                uint32_t bh0 = Bh[kb0 + n], bh1 = Bh[kb1 + n];
                uint32_t bl0 = Bl[kb0 + n], bl1 = Bl[kb1 + n];
                MMA16816(d[j], ah0, ah1, ah2, ah3, bh0, bh1);
                MMA16816(d[j], ah0, ah1, ah2, ah3, bl0, bl1);
                MMA16816(d[j], al0, al1, al2, al3, bh0, bh1);
            }
        }
        if (cc + 1 < 32) {
            storeB(p ^ 1, xa, xb);
            CP_WAIT0();
            __syncthreads();
        }
    }

    // epilogue: D rows -> g_G[ks][src][bh][pl][e][mode]
    float* G = g_G[ks][src][bh];
    int r0 = 16 * w + g, r1 = r0 + 8;
    int pl0 = (r0 >> 6) * 4096, m0 = r0 & 63;
    int pl1 = (r1 >> 6) * 4096, m1 = r1 & 63;
#pragma unroll
    for (int j = 0; j < 8; j++) {
        int e0c = 8 * j + 2 * tg;
        G[pl0 + e0c * 64 + m0]       = d[j][0];
        G[pl0 + (e0c + 1) * 64 + m0] = d[j][1];
        G[pl1 + e0c * 64 + m1]       = d[j][2];
        G[pl1 + (e0c + 1) * 64 + m1] = d[j][3];
    }
}

// ---------------- K2a: projections X = W*G + bias (ksplit sum) ----------------
__global__ void __launch_bounds__(256) k_proj(
    const float* __restrict__ wq_w, const float* __restrict__ wq_b,
    const float* __restrict__ wk_w, const float* __restrict__ wk_b,
    const int* __restrict__ idxq,   const int* __restrict__ idxkv) {
    extern __shared__ float sm[];
    float* sG = sm;          // 8192
    float* sW = sm + 8192;   // 4096

    int bx = blockIdx.x;
    int src = bx >> 7;
    int bh  = bx & 127;
    const float* Wm   = src ? wk_w : wq_w;
    const float* bias = src ? wk_b : wq_b;
    const int*   idx  = src ? idxkv : idxq;
    int tid = threadIdx.x;

#pragma unroll
    for (int r = 0; r < 8; r++) {
        float4 a = ((const float4*)(g_G[0][src][bh]))[r * 256 + tid];
        float4 a1 = ((const float4*)(g_G[1][src][bh]))[r * 256 + tid];
        a.x += a1.x; a.y += a1.y; a.z += a1.z; a.w += a1.w;
        ((float4*)sG)[r * 256 + tid] = a;
    }
#pragma unroll
    for (int r = 0; r < 4; r++)
        ((float4*)sW)[r * 256 + tid] = ((const float4*)Wm)[r * 256 + tid];
    __syncthreads();

    float* Xout = g_X[src][bh];
#pragma unroll 1
    for (int kk = 0; kk < 8; kk++) {
        int pidx = kk * 256 + tid;
        int ep = pidx >> 5, mp = pidx & 31;
        ull ar0 = 0ULL, ar1 = 0ULL, ai0 = 0ULL, ai1 = 0ULL;
#pragma unroll 8
        for (int e = 0; e < 32; e++) {
            ull wd0 = dup2(sW[ep * 64 + e]);
            ull wd1 = dup2(sW[ep * 64 + 32 + e]);
            fma2(ar0, wd0, *(ull*)&sG[e * 64 + mp * 2]);
            fma2(ar1, wd1, *(ull*)&sG[(32 + e) * 64 + mp * 2]);
            fma2(ai0, wd0, *(ull*)&sG[4096 + e * 64 + mp * 2]);
            fma2(ai1, wd1, *(ull*)&sG[4096 + (32 + e) * 64 + mp * 2]);
        }
        float2 arf = unpk(add2(ar0, ar1)), aif = unpk(add2(ai0, ai1));
        float bb = 2048.f * bias[ep];
        if (idx[2 * mp] == 0)     arf.x += bb;
        if (idx[2 * mp + 1] == 0) arf.y += bb;
        *(float2*)&Xout[ep * 64 + mp * 2] = arf;
        *(float2*)&Xout[4096 + ep * 64 + mp * 2] = aif;
    }
}

// ---------------- K2b: scores + tanh + apply -> Z ----------------
__global__ void __launch_bounds__(256) k_attn(const int* __restrict__ idxq) {
    extern __shared__ float sm[];
    float* sXq = sm;            // 2048
    float* sXk = sm + 2048;     // 8192
    float* sS  = sm + 10240;    // 2048

    int bx = blockIdx.x;
    int bh = bx >> 2;
    int xc = bx & 3;
    int x0 = xc * 16;
    int tid = threadIdx.x;

    const float* Xq = g_X[0][bh];
#pragma unroll
    for (int r = 0; r < 2; r++) {
        int idx = r * 256 + tid;
        int p = idx >> 8, rem = idx & 255;
        int e = rem >> 2, c = rem & 3;
        ((float4*)sXq)[idx] = *(const float4*)(Xq + p * 4096 + e * 64 + x0 + c * 4);
    }
    const float4* Xk4 = (const float4*)(g_X[1][bh]);
#pragma unroll
    for (int r = 0; r < 8; r++)
        ((float4*)sXk)[r * 256 + tid] = Xk4[r * 256 + tid];
    __syncthreads();

#pragma unroll 1
    for (int kk = 0; kk < 2; kk++) {
        int pidx = kk * 256 + tid;
        int y = pidx >> 3, xp = pidx & 7;
        ull sr0 = 0ULL, sr1 = 0ULL, si0 = 0ULL, si1 = 0ULL;
#pragma unroll 8
        for (int e = 0; e < 32; e++) {
            ull qr0 = *(ull*)&sXq[e * 16 + xp * 2];
            ull qi0 = *(ull*)&sXq[1024 + e * 16 + xp * 2];
            ull qr1 = *(ull*)&sXq[(32 + e) * 16 + xp * 2];
            ull qi1 = *(ull*)&sXq[1024 + (32 + e) * 16 + xp * 2];
            float kr0 = sXk[e * 64 + y],        ki0 = sXk[4096 + e * 64 + y];
            float kr1 = sXk[(32 + e) * 64 + y], ki1 = sXk[4096 + (32 + e) * 64 + y];
            fma2(sr0, qr0, dup2(kr0)); fma2(sr0, qi0, dup2(-ki0));
            fma2(si0, qr0, dup2(ki0)); fma2(si0, qi0, dup2(kr0));
            fma2(sr1, qr1, dup2(kr1)); fma2(sr1, qi1, dup2(-ki1));
            fma2(si1, qr1, dup2(ki1)); fma2(si1, qi1, dup2(kr1));
        }
        float2 srf = unpk(add2(sr0, sr1)), sif = unpk(add2(si0, si1));
        srf.x = tanhf(srf.x); srf.y = tanhf(srf.y);
        sif.x = tanhf(sif.x); sif.y = tanhf(sif.y);
        *(float2*)&sS[y * 16 + xp * 2] = srf;
        *(float2*)&sS[1024 + y * 16 + xp * 2] = sif;
    }
    __syncthreads();

    float* Zout = g_Z[bh];
#pragma unroll 1
    for (int kk = 0; kk < 2; kk++) {
        int pidx = kk * 256 + tid;
        int e = pidx >> 3, xp = pidx & 7;
        ull zr0 = 0ULL, zr1 = 0ULL, zi0 = 0ULL, zi1 = 0ULL;
#pragma unroll 8
        for (int y = 0; y < 32; y++) {
            ull s_r0 = *(ull*)&sS[y * 16 + xp * 2];
            ull s_i0 = *(ull*)&sS[1024 + y * 16 + xp * 2];
            ull s_r1 = *(ull*)&sS[(32 + y) * 16 + xp * 2];
            ull s_i1 = *(ull*)&sS[1024 + (32 + y) * 16 + xp * 2];
            float kr0 = sXk[e * 64 + y],      ki0 = sXk[4096 + e * 64 + y];
            float kr1 = sXk[e * 64 + 32 + y], ki1 = sXk[4096 + e * 64 + 32 + y];
            fma2(zr0, s_r0, dup2(kr0)); fma2(zr0, s_i0, dup2(-ki0));
            fma2(zi0, s_r0, dup2(ki0)); fma2(zi0, s_i0, dup2(kr0));
            fma2(zr1, s_r1, dup2(kr1)); fma2(zr1, s_i1, dup2(-ki1));
            fma2(zi1, s_r1, dup2(ki1)); fma2(zi1, s_i1, dup2(kr1));
        }
        float2 zrf = unpk(add2(zr0, zr1)), zif = unpk(add2(zi0, zi1));
        *(float2*)&Zout[e * 64 + x0 + xp * 2]        = zrf;
        *(float2*)&Zout[4096 + e * 64 + x0 + xp * 2] = zif;
    }
}

// ---------------- K2c: apply complex weights; parity-grouped Y ----------------
__global__ void __launch_bounds__(256) k_apply(
    const float* __restrict__ W1, const float* __restrict__ W2,
    const int* __restrict__ idxq) {
    extern __shared__ ull smu[];
    ull* sWr = smu;
    ull* sWi = smu + 4096;
    ull* sZ  = smu + 8192;

    int bx = blockIdx.x;
    int h   = bx >> 5;
    int xp2 = bx & 31;
    int x0  = xp2 * 2;
    int tid = threadIdx.x;

    const float* W1h = W1 + (size_t)h * 262144 + x0;
    const float* W2h = W2 + (size_t)h * 262144 + x0;
#pragma unroll
    for (int r = 0; r < 16; r++) {
        int idx = r * 256 + tid;
        sWr[idx] = *(const ull*)(W1h + (size_t)idx * 64);
        sWi[idx] = *(const ull*)(W2h + (size_t)idx * 64);
    }
#pragma unroll
    for (int r = 0; r < 8; r++) {
        int idx = r * 256 + tid;
        int b = idx >> 7, rem = idx & 127;
        sZ[idx] = *(const ull*)(g_Z[b * 8 + h] + (rem >> 6) * 4096 + (rem & 63) * 64 + x0);
    }
    __syncthreads();

    int o  = tid & 63;
    int bq = tid >> 6;

    ull yr[4], yi[4];
#pragma unroll
    for (int j = 0; j < 4; j++) { yr[j] = 0ULL; yi[j] = 0ULL; }

#pragma unroll 4
    for (int e = 0; e < 64; e++) {
        ull wr = sWr[e * 64 + o];
        ull wi = sWi[e * 64 + o];
#pragma unroll
        for (int j = 0; j < 4; j++) {
            int b = bq + j * 4;
            ull zr = sZ[b * 128 + e];
            ull zi = sZ[b * 128 + 64 + e];
            fma2(yr[j], zr, wr); fma2(yr[j], neg2(zi), wi);
            fma2(yi[j], zr, wi); fma2(yi[j], zi, wr);
        }
    }

    const float SC = 1.862645149230957e-9f;  // 2^-29
    int f0 = idxq[x0], f1 = idxq[x0 + 1];
    bool dc0 = (f0 == 0) | (f0 == 1024);
    bool dc1 = (f1 == 0) | (f1 == 1024);
    float ca0 = dc0 ? SC : 2.f * SC;
    float ca1 = dc1 ? SC : 2.f * SC;
    float cb0 = dc0 ? 0.f : -2.f * SC;
    float cb1 = dc1 ? 0.f : -2.f * SC;
    int s0 = g_pmap[x0], s1 = g_pmap[x0 + 1];

#pragma unroll
    for (int j = 0; j < 4; j++) {
        int b = bq + j * 4;
        float* Yout = g_Y + (size_t)(b * 8 + h) * 8192;
        float2 r = unpk(yr[j]), im = unpk(yi[j]);
        Yout[s0 * 64 + o]       = r.x * ca0;
        Yout[(s0 + 1) * 64 + o] = im.x * cb0;
        Yout[s1 * 64 + o]       = r.y * ca1;
        Yout[(s1 + 1) * 64 + o] = im.y * cb1;
    }
}

// ---------------- K3: folded inverse DFT GEMM ----------------
__global__ void __launch_bounds__(256) k_inv2(float* __restrict__ out) {
    __shared__ float As[2][16 * 64];
    __shared__ float Bs[2][16 * 128];

    int bh = blockIdx.y;
    int t0 = blockIdx.x * 128;
    int tid = threadIdx.x;
    int ty = tid >> 4, tx = tid & 15;
    int o0 = ty * 4;
    const float* Yb = g_Y + (size_t)bh * 8192;

    int rA = tid >> 4, cA = (tid & 15) * 4;

    ull acc[2][4][4];
#pragma unroll
    for (int p = 0; p < 2; p++)
#pragma unroll
        for (int i = 0; i < 4; i++)
#pragma unroll
            for (int j = 0; j < 4; j++) acc[p][i][j] = 0ULL;

    float4 pA, pB[2];
    pA = *(const float4*)(Yb + (size_t)rA * 64 + cA);
#pragma unroll
    for (int r = 0; r < 2; r++) {
        int idx = tid + r * 256;
        int row = idx >> 5, col = (idx & 31) * 4;
        pB[r] = *(const float4*)(g_Binv2 + (size_t)row * 1024 + t0 + col);
    }
    *(float4*)&As[0][rA * 64 + cA] = pA;
#pragma unroll
    for (int r = 0; r < 2; r++) {
        int idx = tid + r * 256;
        int row = idx >> 5, col = (idx & 31) * 4;
        *(float4*)&Bs[0][row * 128 + col] = pB[r];
    }
    __syncthreads();

#pragma unroll
    for (int kt = 0; kt < 8; kt++) {
        int p = kt & 1;
        if (kt + 1 < 8) {
            int k0 = (kt + 1) * 16;
            pA = *(const float4*)(Yb + (size_t)(k0 + rA) * 64 + cA);
#pragma unroll
            for (int r = 0; r < 2; r++) {
                int idx = tid + r * 256;
                int row = idx >> 5, col = (idx & 31) * 4;
                pB[r] = *(const float4*)(g_Binv2 + (size_t)(k0 + row) * 1024 + t0 + col);
            }
        }
        const int pg = kt >> 2;
#pragma unroll
        for (int tk = 0; tk < 16; tk++) {
            float4 a = *(float4*)&As[p][tk * 64 + o0];
            ull bv[4];
#pragma unroll
            for (int j = 0; j < 4; j++) bv[j] = *(ull*)&Bs[p][tk * 128 + j * 32 + tx * 2];
            ull ad[4] = {dup2(a.x), dup2(a.y), dup2(a.z), dup2(a.w)};
#pragma unroll
            for (int i = 0; i < 4; i++)
#pragma unroll
                for (int j = 0; j < 4; j++) fma2(acc[pg][i][j], ad[i], bv[j]);
        }
        if (kt + 1 < 8) {
            int np = (kt + 1) & 1;
            *(float4*)&As[np][rA * 64 + cA] = pA;
#pragma unroll
            for (int r = 0; r < 2; r++) {
                int idx = tid + r * 256;
                int row = idx >> 5, col = (idx & 31) * 4;
                *(float4*)&Bs[np][row * 128 + col] = pB[r];
            }
            __syncthreads();
        }
    }

    float* op = out + (size_t)bh * 64 * LSEQ;
#pragma unroll
    for (int i = 0; i < 4; i++) {
        int o = o0 + i;
#pragma unroll
        for (int j = 0; j < 4; j++) {
            int tsub = j * 32 + tx * 2;
            ull E = acc[0][i][j], O = acc[1][i][j];
            *(ull*)(op + (size_t)o * LSEQ + t0 + tsub)        = add2(E, O);
            *(ull*)(op + (size_t)o * LSEQ + 1024 + t0 + tsub) = add2(E, neg2(O));
        }
    }
}

// ---------------- launch ----------------
extern "C" void kernel_launch(void* const* d_in, const int* in_sizes, int n_in,
                              void* d_out, int out_size) {
    const float* q    = (const float*)d_in[0];
    const float* k    = (const float*)d_in[1];
    const float* wq_w = (const float*)d_in[3];
    const float* wq_b = (const float*)d_in[4];
    const float* wk_w = (const float*)d_in[5];
    const float* wk_b = (const float*)d_in[6];
    const float* W1   = (const float*)d_in[9];
    const float* W2   = (const float*)d_in[10];
    const int*  idxq  = (const int*)d_in[11];
    const int*  idxkv = (const int*)d_in[12];
    float* out = (float*)d_out;

    cudaFuncSetAttribute(k_fwd_mma2, cudaFuncAttributeMaxDynamicSharedMemorySize, 60416);
    cudaFuncSetAttribute(k_proj,  cudaFuncAttributeMaxDynamicSharedMemorySize, 49152);
    cudaFuncSetAttribute(k_attn,  cudaFuncAttributeMaxDynamicSharedMemorySize, 49152);
    cudaFuncSetAttribute(k_apply, cudaFuncAttributeMaxDynamicSharedMemorySize, 81920);

    k_init_binv2<<<256, 256>>>(idxq);
    k_init_fm<<<512, 256>>>(idxq, 0);
    k_init_fm<<<512, 256>>>(idxkv, 1);
    k_fwd_mma2<<<512, 256, 60416>>>(q, k);
    k_proj<<<256, 256, 49152>>>(wq_w, wq_b, wk_w, wk_b, idxq, idxkv);
    k_attn<<<512, 256, 49152>>>(idxq);
    k_apply<<<256, 256, 81920>>>(W1, W2, idxq);
    k_inv2<<<dim3(8, 128), 256>>>(out);
}

// round 17
// speedup vs baseline: 1.1066x; 1.0087x over previous
#include <cuda_runtime.h>
#include <cuda_bf16.h>
#include <cstdint>

#define LSEQ 2048
#define NBH 128
typedef unsigned long long ull;

// -------- device scratch --------
__device__ float g_Binv2[128 * 1024];    // [kslot][t<1024] parity-grouped cos/sin
__device__ int   g_pmap[64];             // mode m -> kslot (cos; sin at +1)
__device__ uint32_t g_Fm[2][2][64][2048]; // [src][hi/lo][chunk][m*16+kw] bf16x2 words
__device__ float g_G[2][2][NBH][8192];   // [ks][src][bh][pl][e][m]
__device__ float g_X[2][NBH][8192];      // projected spectra
__device__ float g_Z[NBH][8192];         // attention-applied spectra
__device__ float g_Y[NBH * 8192];        // irDFT coeffs, parity-grouped

// -------- f32x2 helpers --------
__device__ __forceinline__ ull dup2(float x) {
    ull r; asm("mov.b64 %0, {%1, %1};" : "=l"(r) : "f"(x)); return r;
}
__device__ __forceinline__ void fma2(ull& d, ull a, ull b) {
    asm("fma.rn.f32x2 %0, %1, %2, %3;" : "=l"(d) : "l"(a), "l"(b), "l"(d));
}
__device__ __forceinline__ ull add2(ull a, ull b) {
    ull r; asm("add.rn.f32x2 %0, %1, %2;" : "=l"(r) : "l"(a), "l"(b)); return r;
}
__device__ __forceinline__ float2 unpk(ull v) {
    float2 r; asm("mov.b64 {%0, %1}, %2;" : "=f"(r.x), "=f"(r.y) : "l"(v)); return r;
}
__device__ __forceinline__ ull neg2(ull v) { return v ^ 0x8000000080000000ULL; }

// -------- bf16 mma + cp.async (baseline PTX sm_80+, no 'a' features) --------
#define MMA16816(d, a0, a1, a2, a3, b0, b1) \
    asm volatile("mma.sync.aligned.m16n8k16.row.col.f32.bf16.bf16.f32 " \
                 "{%0,%1,%2,%3},{%4,%5,%6,%7},{%8,%9},{%0,%1,%2,%3};" \
                 : "+f"((d)[0]), "+f"((d)[1]), "+f"((d)[2]), "+f"((d)[3]) \
                 : "r"(a0), "r"(a1), "r"(a2), "r"(a3), "r"(b0), "r"(b1))

__device__ __forceinline__ uint32_t smem_u32(const void* p) {
    uint32_t a;
    asm("{ .reg .u64 t; cvta.to.shared.u64 t, %1; cvt.u32.u64 %0, t; }" : "=r"(a) : "l"(p));
    return a;
}
__device__ __forceinline__ void cpasync16(uint32_t dst, const void* src) {
    asm volatile("cp.async.ca.shared.global [%0], [%1], 16;" :: "r"(dst), "l"(src));
}
#define CP_COMMIT() asm volatile("cp.async.commit_group;" ::: "memory")
#define CP_WAIT0()  asm volatile("cp.async.wait_group 0;" ::: "memory")

__device__ __forceinline__ uint32_t pack_bf16x2(float lo, float hi) {
    __nv_bfloat162 v;
    v.x = __float2bfloat16(lo);
    v.y = __float2bfloat16(hi);
    return *(uint32_t*)&v;
}

// ---------------- init: parity-grouped inverse basis ----------------
__global__ void k_init_binv2(const int* __restrict__ idxq) {
    __shared__ int sidx[64];
    int tid = threadIdx.x;
    if (tid < 64) sidx[tid] = idxq[tid];
    __syncthreads();
    int gidx = blockIdx.x * blockDim.x + tid;
    if (gidx >= 1024 * 64) return;
    int t = gidx >> 6, m = gidx & 63;
    int f = sidx[m];
    int par = f & 1;
    int rank = 0;
    for (int mm = 0; mm < m; mm++) rank += ((sidx[mm] & 1) == par);
    int slot = par * 64 + 2 * rank;
    int r = (f * t) & (LSEQ - 1);
    float sn, cs;
    sincospif((float)r * (1.0f / 1024.0f), &sn, &cs);
    g_Binv2[slot * 1024 + t]       = cs;
    g_Binv2[(slot + 1) * 1024 + t] = sn;
    if (t == 0) g_pmap[m] = slot;
}

// ---------------- init: bf16 hi/lo forward basis tables ----------------
__global__ void k_init_fm(const int* __restrict__ idx, int src) {
    int gidx = blockIdx.x * blockDim.x + threadIdx.x;
    if (gidx >= 64 * 128 * 16) return;
    int c  = gidx >> 11;
    int m  = (gidx >> 4) & 127;
    int kw = gidx & 15;
    int f = __ldg(&idx[m & 63]);
    int t0 = c * 32 + 2 * kw;
    float v[2];
#pragma unroll
    for (int u = 0; u < 2; u++) {
        int r = (f * (t0 + u)) & (LSEQ - 1);
        float sn, cs;
        sincospif((float)r * (1.0f / 1024.0f), &sn, &cs);
        v[u] = (m < 64) ? cs : -sn;
    }
    float h0 = __bfloat162float(__float2bfloat16(v[0]));
    float h1 = __bfloat162float(__float2bfloat16(v[1]));
    g_Fm[src][0][c][m * 16 + kw] = pack_bf16x2(v[0], v[1]);
    g_Fm[src][1][c][m * 16 + kw] = pack_bf16x2(v[0] - h0, v[1] - h1);
}

// ---------------- K1: pipelined mma.sync forward DFT, 32x32 warp tiles ----------------
// grid 512: (ks, bh, src). 256 thr = 8 warps as 4 m-groups x 2 n-groups.
// Per warp: rows 32*wm..+31 (2 m16 tiles), cols 32*wn..+31 (4 n8 tiles).
// Per k16 step: A 16 words + B 16 words + 24 MMA (vs 16x64: A 8 + B 32).
__global__ void __launch_bounds__(256) k_fwd_mma3(const float* __restrict__ q,
                                                  const float* __restrict__ kk_) {
    extern __shared__ uint32_t smw[];
    const int WB = 7424;            // words per buffer
    const int OAL = 2560, OBH = 5120, OBL = 6272;

    int bx = blockIdx.x;
    int ks  = bx & 1;
    int bh  = (bx >> 1) & 127;
    int src = bx >> 8;
    const float* x = (src == 0 ? q : kk_)
                   + (size_t)(bh >> 3) * (LSEQ * 512) + (bh & 7) * 64;
    const uint32_t* TAh = &g_Fm[src][0][0][0];
    const uint32_t* TAl = &g_Fm[src][1][0][0];

    int tid = threadIdx.x;
    int w = tid >> 5, lane = tid & 31;
    int g = lane >> 2, tg = lane & 3;
    int wm = w >> 1, wn = w & 1;

    // A cp.async indices (2 uint4/thread/table)
    int iA0 = tid, iA1 = tid + 256;
    int rowA0i = iA0 >> 2, qdA0 = iA0 & 3;
    int rowA1i = iA1 >> 2, qdA1 = iA1 & 3;
    uint32_t dAh0 = smem_u32(smw) + (rowA0i * 20 + qdA0 * 4) * 4;
    uint32_t dAh1 = smem_u32(smw) + (rowA1i * 20 + qdA1 * 4) * 4;

    // B staging indices
    int kpL = tid >> 4;
    int e0L = (tid & 15) * 4;

    float d[2][4][4];
#pragma unroll
    for (int i = 0; i < 2; i++)
#pragma unroll
        for (int j = 0; j < 4; j++)
#pragma unroll
            for (int u = 0; u < 4; u++) d[i][j][u] = 0.f;

    auto issueA = [&](int c, int p) {
        uint32_t off = (uint32_t)p * WB * 4;
        const char* sH = (const char*)(TAh + (size_t)c * 2048);
        const char* sL = (const char*)(TAl + (size_t)c * 2048);
        cpasync16(dAh0 + off, sH + iA0 * 16);
        cpasync16(dAh1 + off, sH + iA1 * 16);
        cpasync16(dAh0 + off + OAL * 4, sL + iA0 * 16);
        cpasync16(dAh1 + off + OAL * 4, sL + iA1 * 16);
        CP_COMMIT();
    };
    auto loadB = [&](int c, float4& xa, float4& xb) {
        const float* xr0 = x + (size_t)(c * 32 + 2 * kpL) * 512;
        xa = *(const float4*)(xr0 + e0L);
        xb = *(const float4*)(xr0 + 512 + e0L);
    };
    auto storeB = [&](int p, const float4& xa, const float4& xb) {
        float av[4] = {xa.x, xa.y, xa.z, xa.w};
        float bv[4] = {xb.x, xb.y, xb.z, xb.w};
        uint32_t hw[4], lw[4];
#pragma unroll
        for (int u = 0; u < 4; u++) {
            float ah = __bfloat162float(__float2bfloat16(av[u]));
            float bhf = __bfloat162float(__float2bfloat16(bv[u]));
            hw[u] = pack_bf16x2(av[u], bv[u]);
            lw[u] = pack_bf16x2(av[u] - ah, bv[u] - bhf);
        }
        uint32_t* B = smw + p * WB;
        *(uint4*)&B[OBH + kpL * 72 + e0L] = make_uint4(hw[0], hw[1], hw[2], hw[3]);
        *(uint4*)&B[OBL + kpL * 72 + e0L] = make_uint4(lw[0], lw[1], lw[2], lw[3]);
    };

    // prologue
    float4 xa, xb;
    issueA(ks * 32, 0);
    loadB(ks * 32, xa, xb);
    storeB(0, xa, xb);
    CP_WAIT0();
    __syncthreads();

    int rowA0 = (32 * wm + g) * 20;
    int rowA1 = (32 * wm + 16 + g) * 20;

    for (int cc = 0; cc < 32; cc++) {
        int p = cc & 1;
        if (cc + 1 < 32) {
            issueA(ks * 32 + cc + 1, p ^ 1);
            loadB(ks * 32 + cc + 1, xa, xb);
        }
        uint32_t* Ah = smw + p * WB;
        uint32_t* Al = Ah + OAL;
        uint32_t* Bh = Ah + OBH;
        uint32_t* Bl = Ah + OBL;
#pragma unroll
        for (int s = 0; s < 2; s++) {
            int ka = 8 * s + tg;
            uint32_t ah[2][4], al[2][4];
            ah[0][0] = Ah[rowA0 + ka];       ah[0][1] = Ah[rowA0 + 160 + ka];
            ah[0][2] = Ah[rowA0 + ka + 4];   ah[0][3] = Ah[rowA0 + 160 + ka + 4];
            ah[1][0] = Ah[rowA1 + ka];       ah[1][1] = Ah[rowA1 + 160 + ka];
            ah[1][2] = Ah[rowA1 + ka + 4];   ah[1][3] = Ah[rowA1 + 160 + ka + 4];
            al[0][0] = Al[rowA0 + ka];       al[0][1] = Al[rowA0 + 160 + ka];
            al[0][2] = Al[rowA0 + ka + 4];   al[0][3] = Al[rowA0 + 160 + ka + 4];
            al[1][0] = Al[rowA1 + ka];       al[1][1] = Al[rowA1 + 160 + ka];
            al[1][2] = Al[rowA1 + ka + 4];   al[1][3] = Al[rowA1 + 160 + ka + 4];
            int kb0 = (8 * s + tg) * 72;
            int kb1 = kb0 + 288;             // +4*72
#pragma unroll
            for (int j = 0; j < 4; j++) {
                int n = 32 * wn + 8 * j + g;
                uint32_t bh0 = Bh[kb0 + n], bh1 = Bh[kb1 + n];
                uint32_t bl0 = Bl[kb0 + n], bl1 = Bl[kb1 + n];
#pragma unroll
                for (int i = 0; i < 2; i++) {
                    MMA16816(d[i][j], ah[i][0], ah[i][1], ah[i][2], ah[i][3], bh0, bh1);
                    MMA16816(d[i][j], ah[i][0], ah[i][1], ah[i][2], ah[i][3], bl0, bl1);
                    MMA16816(d[i][j], al[i][0], al[i][1], al[i][2], al[i][3], bh0, bh1);
                }
            }
        }
        if (cc + 1 < 32) {
            storeB(p ^ 1, xa, xb);
            CP_WAIT0();
            __syncthreads();
        }
    }

    // epilogue: rows 32wm+16i+g (+8), cols 32wn+8j+2tg (+1)
    float* G = g_G[ks][src][bh];
#pragma unroll
    for (int i = 0; i < 2; i++) {
        int r0 = 32 * wm + 16 * i + g, r1 = r0 + 8;
        int pl0 = (r0 >> 6) * 4096, m0 = r0 & 63;
        int pl1 = (r1 >> 6) * 4096, m1 = r1 & 63;
#pragma unroll
        for (int j = 0; j < 4; j++) {
            int e0c = 32 * wn + 8 * j + 2 * tg;
            G[pl0 + e0c * 64 + m0]       = d[i][j][0];
            G[pl0 + (e0c + 1) * 64 + m0] = d[i][j][1];
            G[pl1 + e0c * 64 + m1]       = d[i][j][2];
            G[pl1 + (e0c + 1) * 64 + m1] = d[i][j][3];
        }
    }
}

// ---------------- K2a: projections X = W*G + bias (ksplit sum) ----------------
__global__ void __launch_bounds__(256) k_proj(
    const float* __restrict__ wq_w, const float* __restrict__ wq_b,
    const float* __restrict__ wk_w, const float* __restrict__ wk_b,
    const int* __restrict__ idxq,   const int* __restrict__ idxkv) {
    extern __shared__ float sm[];
    float* sG = sm;          // 8192
    float* sW = sm + 8192;   // 4096

    int bx = blockIdx.x;
    int src = bx >> 7;
    int bh  = bx & 127;
    const float* Wm   = src ? wk_w : wq_w;
    const float* bias = src ? wk_b : wq_b;
    const int*   idx  = src ? idxkv : idxq;
    int tid = threadIdx.x;

#pragma unroll
    for (int r = 0; r < 8; r++) {
        float4 a = ((const float4*)(g_G[0][src][bh]))[r * 256 + tid];
        float4 a1 = ((const float4*)(g_G[1][src][bh]))[r * 256 + tid];
        a.x += a1.x; a.y += a1.y; a.z += a1.z; a.w += a1.w;
        ((float4*)sG)[r * 256 + tid] = a;
    }
#pragma unroll
    for (int r = 0; r < 4; r++)
        ((float4*)sW)[r * 256 + tid] = ((const float4*)Wm)[r * 256 + tid];
    __syncthreads();

    float* Xout = g_X[src][bh];
#pragma unroll 1
    for (int kk = 0; kk < 8; kk++) {
        int pidx = kk * 256 + tid;
        int ep = pidx >> 5, mp = pidx & 31;
        ull ar0 = 0ULL, ar1 = 0ULL, ai0 = 0ULL, ai1 = 0ULL;
#pragma unroll 8
        for (int e = 0; e < 32; e++) {
            ull wd0 = dup2(sW[ep * 64 + e]);
            ull wd1 = dup2(sW[ep * 64 + 32 + e]);
            fma2(ar0, wd0, *(ull*)&sG[e * 64 + mp * 2]);
            fma2(ar1, wd1, *(ull*)&sG[(32 + e) * 64 + mp * 2]);
            fma2(ai0, wd0, *(ull*)&sG[4096 + e * 64 + mp * 2]);
            fma2(ai1, wd1, *(ull*)&sG[4096 + (32 + e) * 64 + mp * 2]);
        }
        float2 arf = unpk(add2(ar0, ar1)), aif = unpk(add2(ai0, ai1));
        float bb = 2048.f * bias[ep];
        if (idx[2 * mp] == 0)     arf.x += bb;
        if (idx[2 * mp + 1] == 0) arf.y += bb;
        *(float2*)&Xout[ep * 64 + mp * 2] = arf;
        *(float2*)&Xout[4096 + ep * 64 + mp * 2] = aif;
    }
}

// ---------------- K2b: scores + tanh + apply -> Z ----------------
__global__ void __launch_bounds__(256) k_attn(const int* __restrict__ idxq) {
    extern __shared__ float sm[];
    float* sXq = sm;            // 2048
    float* sXk = sm + 2048;     // 8192
    float* sS  = sm + 10240;    // 2048

    int bx = blockIdx.x;
    int bh = bx >> 2;
    int xc = bx & 3;
    int x0 = xc * 16;
    int tid = threadIdx.x;

    const float* Xq = g_X[0][bh];
#pragma unroll
    for (int r = 0; r < 2; r++) {
        int idx = r * 256 + tid;
        int p = idx >> 8, rem = idx & 255;
        int e = rem >> 2, c = rem & 3;
        ((float4*)sXq)[idx] = *(const float4*)(Xq + p * 4096 + e * 64 + x0 + c * 4);
    }
    const float4* Xk4 = (const float4*)(g_X[1][bh]);
#pragma unroll
    for (int r = 0; r < 8; r++)
        ((float4*)sXk)[r * 256 + tid] = Xk4[r * 256 + tid];
    __syncthreads();

#pragma unroll 1
    for (int kk = 0; kk < 2; kk++) {
        int pidx = kk * 256 + tid;
        int y = pidx >> 3, xp = pidx & 7;
        ull sr0 = 0ULL, sr1 = 0ULL, si0 = 0ULL, si1 = 0ULL;
#pragma unroll 8
        for (int e = 0; e < 32; e++) {
            ull qr0 = *(ull*)&sXq[e * 16 + xp * 2];
            ull qi0 = *(ull*)&sXq[1024 + e * 16 + xp * 2];
            ull qr1 = *(ull*)&sXq[(32 + e) * 16 + xp * 2];
            ull qi1 = *(ull*)&sXq[1024 + (32 + e) * 16 + xp * 2];
            float kr0 = sXk[e * 64 + y],        ki0 = sXk[4096 + e * 64 + y];
            float kr1 = sXk[(32 + e) * 64 + y], ki1 = sXk[4096 + (32 + e) * 64 + y];
            fma2(sr0, qr0, dup2(kr0)); fma2(sr0, qi0, dup2(-ki0));
            fma2(si0, qr0, dup2(ki0)); fma2(si0, qi0, dup2(kr0));
            fma2(sr1, qr1, dup2(kr1)); fma2(sr1, qi1, dup2(-ki1));
            fma2(si1, qr1, dup2(ki1)); fma2(si1, qi1, dup2(kr1));
        }
        float2 srf = unpk(add2(sr0, sr1)), sif = unpk(add2(si0, si1));
        srf.x = tanhf(srf.x); srf.y = tanhf(srf.y);
        sif.x = tanhf(sif.x); sif.y = tanhf(sif.y);
        *(float2*)&sS[y * 16 + xp * 2] = srf;
        *(float2*)&sS[1024 + y * 16 + xp * 2] = sif;
    }
    __syncthreads();

    float* Zout = g_Z[bh];
#pragma unroll 1
    for (int kk = 0; kk < 2; kk++) {
        int pidx = kk * 256 + tid;
        int e = pidx >> 3, xp = pidx & 7;
        ull zr0 = 0ULL, zr1 = 0ULL, zi0 = 0ULL, zi1 = 0ULL;
#pragma unroll 8
        for (int y = 0; y < 32; y++) {
            ull s_r0 = *(ull*)&sS[y * 16 + xp * 2];
            ull s_i0 = *(ull*)&sS[1024 + y * 16 + xp * 2];
            ull s_r1 = *(ull*)&sS[(32 + y) * 16 + xp * 2];
            ull s_i1 = *(ull*)&sS[1024 + (32 + y) * 16 + xp * 2];
            float kr0 = sXk[e * 64 + y],      ki0 = sXk[4096 + e * 64 + y];
            float kr1 = sXk[e * 64 + 32 + y], ki1 = sXk[4096 + e * 64 + 32 + y];
            fma2(zr0, s_r0, dup2(kr0)); fma2(zr0, s_i0, dup2(-ki0));
            fma2(zi0, s_r0, dup2(ki0)); fma2(zi0, s_i0, dup2(kr0));
            fma2(zr1, s_r1, dup2(kr1)); fma2(zr1, s_i1, dup2(-ki1));
            fma2(zi1, s_r1, dup2(ki1)); fma2(zi1, s_i1, dup2(kr1));
        }
        float2 zrf = unpk(add2(zr0, zr1)), zif = unpk(add2(zi0, zi1));
        *(float2*)&Zout[e * 64 + x0 + xp * 2]        = zrf;
        *(float2*)&Zout[4096 + e * 64 + x0 + xp * 2] = zif;
    }
}

// ---------------- K2c: apply complex weights; parity-grouped Y ----------------
__global__ void __launch_bounds__(256) k_apply(
    const float* __restrict__ W1, const float* __restrict__ W2,
    const int* __restrict__ idxq) {
    extern __shared__ ull smu[];
    ull* sWr = smu;
    ull* sWi = smu + 4096;
    ull* sZ  = smu + 8192;

    int bx = blockIdx.x;
    int h   = bx >> 5;
    int xp2 = bx & 31;
    int x0  = xp2 * 2;
    int tid = threadIdx.x;

    const float* W1h = W1 + (size_t)h * 262144 + x0;
    const float* W2h = W2 + (size_t)h * 262144 + x0;
#pragma unroll
    for (int r = 0; r < 16; r++) {
        int idx = r * 256 + tid;
        sWr[idx] = *(const ull*)(W1h + (size_t)idx * 64);
        sWi[idx] = *(const ull*)(W2h + (size_t)idx * 64);
    }
#pragma unroll
    for (int r = 0; r < 8; r++) {
        int idx = r * 256 + tid;
        int b = idx >> 7, rem = idx & 127;
        sZ[idx] = *(const ull*)(g_Z[b * 8 + h] + (rem >> 6) * 4096 + (rem & 63) * 64 + x0);
    }
    __syncthreads();

    int o  = tid & 63;
    int bq = tid >> 6;

    ull yr[4], yi[4];
#pragma unroll
    for (int j = 0; j < 4; j++) { yr[j] = 0ULL; yi[j] = 0ULL; }

#pragma unroll 4
    for (int e = 0; e < 64; e++) {
        ull wr = sWr[e * 64 + o];
        ull wi = sWi[e * 64 + o];
#pragma unroll
        for (int j = 0; j < 4; j++) {
            int b = bq + j * 4;
            ull zr = sZ[b * 128 + e];
            ull zi = sZ[b * 128 + 64 + e];
            fma2(yr[j], zr, wr); fma2(yr[j], neg2(zi), wi);
            fma2(yi[j], zr, wi); fma2(yi[j], zi, wr);
        }
    }

    const float SC = 1.862645149230957e-9f;  // 2^-29
    int f0 = idxq[x0], f1 = idxq[x0 + 1];
    bool dc0 = (f0 == 0) | (f0 == 1024);
    bool dc1 = (f1 == 0) | (f1 == 1024);
    float ca0 = dc0 ? SC : 2.f * SC;
    float ca1 = dc1 ? SC : 2.f * SC;
    float cb0 = dc0 ? 0.f : -2.f * SC;
    float cb1 = dc1 ? 0.f : -2.f * SC;
    int s0 = g_pmap[x0], s1 = g_pmap[x0 + 1];

#pragma unroll
    for (int j = 0; j < 4; j++) {
        int b = bq + j * 4;
        float* Yout = g_Y + (size_t)(b * 8 + h) * 8192;
        float2 r = unpk(yr[j]), im = unpk(yi[j]);
        Yout[s0 * 64 + o]       = r.x * ca0;
        Yout[(s0 + 1) * 64 + o] = im.x * cb0;
        Yout[s1 * 64 + o]       = r.y * ca1;
        Yout[(s1 + 1) * 64 + o] = im.y * cb1;
    }
}

// ---------------- K3: folded inverse DFT GEMM ----------------
__global__ void __launch_bounds__(256) k_inv2(float* __restrict__ out) {
    __shared__ float As[2][16 * 64];
    __shared__ float Bs[2][16 * 128];

    int bh = blockIdx.y;
    int t0 = blockIdx.x * 128;
    int tid = threadIdx.x;
    int ty = tid >> 4, tx = tid & 15;
    int o0 = ty * 4;
    const float* Yb = g_Y + (size_t)bh * 8192;

    int rA = tid >> 4, cA = (tid & 15) * 4;

    ull acc[2][4][4];
#pragma unroll
    for (int p = 0; p < 2; p++)
#pragma unroll
        for (int i = 0; i < 4; i++)
#pragma unroll
            for (int j = 0; j < 4; j++) acc[p][i][j] = 0ULL;

    float4 pA, pB[2];
    pA = *(const float4*)(Yb + (size_t)rA * 64 + cA);
#pragma unroll
    for (int r = 0; r < 2; r++) {
        int idx = tid + r * 256;
        int row = idx >> 5, col = (idx & 31) * 4;
        pB[r] = *(const float4*)(g_Binv2 + (size_t)row * 1024 + t0 + col);
    }
    *(float4*)&As[0][rA * 64 + cA] = pA;
#pragma unroll
    for (int r = 0; r < 2; r++) {
        int idx = tid + r * 256;
        int row = idx >> 5, col = (idx & 31) * 4;
        *(float4*)&Bs[0][row * 128 + col] = pB[r];
    }
    __syncthreads();

#pragma unroll
    for (int kt = 0; kt < 8; kt++) {
        int p = kt & 1;
        if (kt + 1 < 8) {
            int k0 = (kt + 1) * 16;
            pA = *(const float4*)(Yb + (size_t)(k0 + rA) * 64 + cA);
#pragma unroll
            for (int r = 0; r < 2; r++) {
                int idx = tid + r * 256;
                int row = idx >> 5, col = (idx & 31) * 4;
                pB[r] = *(const float4*)(g_Binv2 + (size_t)(k0 + row) * 1024 + t0 + col);
            }
        }
        const int pg = kt >> 2;
#pragma unroll
        for (int tk = 0; tk < 16; tk++) {
            float4 a = *(float4*)&As[p][tk * 64 + o0];
            ull bv[4];
#pragma unroll
            for (int j = 0; j < 4; j++) bv[j] = *(ull*)&Bs[p][tk * 128 + j * 32 + tx * 2];
            ull ad[4] = {dup2(a.x), dup2(a.y), dup2(a.z), dup2(a.w)};
#pragma unroll
            for (int i = 0; i < 4; i++)
#pragma unroll
                for (int j = 0; j < 4; j++) fma2(acc[pg][i][j], ad[i], bv[j]);
        }
        if (kt + 1 < 8) {
            int np = (kt + 1) & 1;
            *(float4*)&As[np][rA * 64 + cA] = pA;
#pragma unroll
            for (int r = 0; r < 2; r++) {
                int idx = tid + r * 256;
                int row = idx >> 5, col = (idx & 31) * 4;
                *(float4*)&Bs[np][row * 128 + col] = pB[r];
            }
            __syncthreads();
        }
    }

    float* op = out + (size_t)bh * 64 * LSEQ;
#pragma unroll
    for (int i = 0; i < 4; i++) {
        int o = o0 + i;
#pragma unroll
        for (int j = 0; j < 4; j++) {
            int tsub = j * 32 + tx * 2;
            ull E = acc[0][i][j], O = acc[1][i][j];
            *(ull*)(op + (size_t)o * LSEQ + t0 + tsub)        = add2(E, O);
            *(ull*)(op + (size_t)o * LSEQ + 1024 + t0 + tsub) = add2(E, neg2(O));
        }
    }
}

// ---------------- launch ----------------
extern "C" void kernel_launch(void* const* d_in, const int* in_sizes, int n_in,
                              void* d_out, int out_size) {
    const float* q    = (const float*)d_in[0];
    const float* k    = (const float*)d_in[1];
    const float* wq_w = (const float*)d_in[3];
    const float* wq_b = (const float*)d_in[4];
    const float* wk_w = (const float*)d_in[5];
    const float* wk_b = (const float*)d_in[6];
    const float* W1   = (const float*)d_in[9];
    const float* W2   = (const float*)d_in[10];
    const int*  idxq  = (const int*)d_in[11];
    const int*  idxkv = (const int*)d_in[12];
    float* out = (float*)d_out;

    cudaFuncSetAttribute(k_fwd_mma3, cudaFuncAttributeMaxDynamicSharedMemorySize, 60416);
    cudaFuncSetAttribute(k_proj,  cudaFuncAttributeMaxDynamicSharedMemorySize, 49152);
    cudaFuncSetAttribute(k_attn,  cudaFuncAttributeMaxDynamicSharedMemorySize, 49152);
    cudaFuncSetAttribute(k_apply, cudaFuncAttributeMaxDynamicSharedMemorySize, 81920);

    k_init_binv2<<<256, 256>>>(idxq);
    k_init_fm<<<512, 256>>>(idxq, 0);
    k_init_fm<<<512, 256>>>(idxkv, 1);
    k_fwd_mma3<<<512, 256, 60416>>>(q, k);
    k_proj<<<256, 256, 49152>>>(wq_w, wq_b, wk_w, wk_b, idxq, idxkv);
    k_attn<<<512, 256, 49152>>>(idxq);
    k_apply<<<256, 256, 81920>>>(W1, W2, idxq);
    k_inv2<<<dim3(8, 128), 256>>>(out);
}